// round 5
// baseline (speedup 1.0000x reference)
#include <cuda_runtime.h>
#include <cuda_bf16.h>
#include <math.h>

// ---------------- Problem constants ----------------
#define B      8
#define S_P    128
#define S_T    64
#define S_V    64
#define SEQ    256          // S_P + S_T + S_V
#define DMODEL 768
#define DLLM   4096
#define NH     32
#define HD     128
#define DFF    11008
#define NLAYER 2
#define NTOK   (B*SEQ)      // 2048
#define EPSRMS 1e-5f

// ---------------- Scratch (device globals; no allocation allowed) ----------------
__device__ float g_h [NTOK*DLLM];                 // residual stream
__device__ float g_x [NTOK*DLLM];                 // normed activations
__device__ float g_q [NTOK*DLLM];
__device__ float g_k [NTOK*DLLM];
__device__ float g_v [NTOK*DLLM];
__device__ float g_o [NTOK*DLLM];
__device__ float g_sc[B*NH*SEQ*SEQ];              // attention scores / probs
__device__ float g_ff[NTOK*DFF];                  // FFN gate / fused buffer
__device__ float g_pool[B*DLLM];
__device__ float g_y1[B*768];

__device__ __forceinline__ float siluf(float x) { return x / (1.f + expf(-x)); }

// ---------------- Generic tiled SGEMM ----------------
// C[M,N] (+)= A[M,K] @ B[K,N] (+bias), row-major everywhere.
// Row remap for scattering into the concatenated sequence:
//   orow = (r / rpbi) * rpbo + roff + (r % rpbi)
// EPI: 0 = store, 1 = C += acc, 2 = C = silu(C_old) * acc   (SwiGLU fuse)
template<int EPI>
__global__ __launch_bounds__(256)
void sgemm_kernel(int M, int N, int K,
                  const float* __restrict__ A,
                  const float* __restrict__ Bm,
                  const float* __restrict__ bias,
                  float* __restrict__ C,
                  int rpbi, int rpbo, int roff)
{
    __shared__ float As[8][128];   // [k][m]  (transposed on load)
    __shared__ float Bs[8][128];   // [k][n]

    const int bx = blockIdx.x;     // N tile
    const int by = blockIdx.y;     // M tile
    const int tid = threadIdx.x;
    const int tx = tid & 15;       // 0..15 -> 8 cols each
    const int ty = tid >> 4;       // 0..15 -> 8 rows each

    const int aRow = tid >> 1;            // 0..127
    const int aCol = (tid & 1) * 4;       // 0 or 4
    const int bRow = tid >> 5;            // 0..7
    const int bCol = (tid & 31) * 4;      // 0..124

    const float* Ab = A + (size_t)(by * 128) * K;
    const float* Bb = Bm + (size_t)(bx * 128);

    float acc[8][8];
    #pragma unroll
    for (int i = 0; i < 8; i++)
        #pragma unroll
        for (int j = 0; j < 8; j++) acc[i][j] = 0.f;

    for (int k0 = 0; k0 < K; k0 += 8) {
        // Load A tile (transpose into As[k][m])
        float4 av = *(const float4*)(Ab + (size_t)aRow * K + k0 + aCol);
        As[aCol + 0][aRow] = av.x;
        As[aCol + 1][aRow] = av.y;
        As[aCol + 2][aRow] = av.z;
        As[aCol + 3][aRow] = av.w;
        // Load B tile
        float4 bv = *(const float4*)(Bb + (size_t)(k0 + bRow) * N + bCol);
        *(float4*)&Bs[bRow][bCol] = bv;
        __syncthreads();

        #pragma unroll
        for (int kk = 0; kk < 8; kk++) {
            float a[8], b[8];
            *(float4*)(a)     = *(const float4*)&As[kk][ty * 8];
            *(float4*)(a + 4) = *(const float4*)&As[kk][ty * 8 + 4];
            *(float4*)(b)     = *(const float4*)&Bs[kk][tx * 8];
            *(float4*)(b + 4) = *(const float4*)&Bs[kk][tx * 8 + 4];
            #pragma unroll
            for (int i = 0; i < 8; i++)
                #pragma unroll
                for (int j = 0; j < 8; j++)
                    acc[i][j] = fmaf(a[i], b[j], acc[i][j]);
        }
        __syncthreads();
    }

    const int col0 = bx * 128 + tx * 8;
    float bseg[8];
    if (bias) {
        *(float4*)(bseg)     = *(const float4*)(bias + col0);
        *(float4*)(bseg + 4) = *(const float4*)(bias + col0 + 4);
    } else {
        #pragma unroll
        for (int j = 0; j < 8; j++) bseg[j] = 0.f;
    }

    #pragma unroll
    for (int i = 0; i < 8; i++) {
        int r = by * 128 + ty * 8 + i;
        int orow = (r / rpbi) * rpbo + roff + (r % rpbi);
        float* dst = C + (size_t)orow * N + col0;
        #pragma unroll
        for (int half = 0; half < 2; half++) {
            float4 val = make_float4(acc[i][half*4+0] + bseg[half*4+0],
                                     acc[i][half*4+1] + bseg[half*4+1],
                                     acc[i][half*4+2] + bseg[half*4+2],
                                     acc[i][half*4+3] + bseg[half*4+3]);
            if (EPI == 0) {
                *(float4*)(dst + half*4) = val;
            } else if (EPI == 1) {
                float4 c = *(float4*)(dst + half*4);
                c.x += val.x; c.y += val.y; c.z += val.z; c.w += val.w;
                *(float4*)(dst + half*4) = c;
            } else {
                float4 gte = *(float4*)(dst + half*4);   // gate values
                gte.x = siluf(gte.x) * val.x;
                gte.y = siluf(gte.y) * val.y;
                gte.z = siluf(gte.z) * val.z;
                gte.w = siluf(gte.w) * val.w;
                *(float4*)(dst + half*4) = gte;
            }
        }
    }
}

// ---------------- Embedding gather (prompt ids) ----------------
__global__ __launch_bounds__(256)
void embed_kernel(const int* __restrict__ ids, const float* __restrict__ table,
                  float* __restrict__ h)
{
    int t = blockIdx.x;                 // 0..B*S_P-1
    int b = t >> 7, p = t & 127;
    int id = ids[t];
    const float4* src = (const float4*)(table + (size_t)id * DLLM);
    float4* dst = (float4*)(h + ((size_t)b * SEQ + p) * DLLM);
    for (int i = threadIdx.x; i < DLLM / 4; i += 256) dst[i] = src[i];
}

// ---------------- RMSNorm (one block per token) ----------------
__global__ __launch_bounds__(256)
void rmsnorm_kernel(const float* __restrict__ in, const float* __restrict__ w,
                    float* __restrict__ out)
{
    size_t t = blockIdx.x;
    const float4* xp = (const float4*)(in + t * DLLM);
    __shared__ float red[8];
    float ss = 0.f;
    for (int i = threadIdx.x; i < DLLM / 4; i += 256) {
        float4 v = xp[i];
        ss += v.x*v.x + v.y*v.y + v.z*v.z + v.w*v.w;
    }
    #pragma unroll
    for (int o = 16; o; o >>= 1) ss += __shfl_xor_sync(0xffffffffu, ss, o);
    if ((threadIdx.x & 31) == 0) red[threadIdx.x >> 5] = ss;
    __syncthreads();
    if (threadIdx.x < 32) {
        float v = (threadIdx.x < 8) ? red[threadIdx.x] : 0.f;
        #pragma unroll
        for (int o = 4; o; o >>= 1) v += __shfl_xor_sync(0xffffffffu, v, o);
        if (threadIdx.x == 0) red[0] = v;
    }
    __syncthreads();
    float r = rsqrtf(red[0] / (float)DLLM + EPSRMS);
    const float4* wp = (const float4*)w;
    float4* op = (float4*)(out + t * DLLM);
    for (int i = threadIdx.x; i < DLLM / 4; i += 256) {
        float4 v = xp[i], wv = wp[i];
        op[i] = make_float4(v.x*r*wv.x, v.y*r*wv.y, v.z*r*wv.z, v.w*r*wv.w);
    }
}

// ---------------- RoPE (HF layout) applied in-place to q and k ----------------
__global__ __launch_bounds__(256)
void rope_kernel(float* __restrict__ q, float* __restrict__ k)
{
    int t = blockIdx.x;                  // token 0..NTOK-1
    int pos = t & (SEQ - 1);             // position within sequence
    const float LOG_THETA = 9.210340371976184f;  // ln(10000)
    for (int it = 0; it < 8; it++) {
        int p = threadIdx.x + it * 256;  // 0..2047 = (h, j)
        int hh = p >> 6, j = p & 63;
        float inv_freq = expf(-(float)j * (LOG_THETA / 64.f));
        float ang = (float)pos * inv_freq;
        float c = cosf(ang), s = sinf(ang);
        size_t base = (size_t)t * DLLM + hh * HD + j;
        float x1 = q[base], x2 = q[base + 64];
        q[base]      = x1 * c - x2 * s;
        q[base + 64] = x2 * c + x1 * s;
        x1 = k[base]; x2 = k[base + 64];
        k[base]      = x1 * c - x2 * s;
        k[base + 64] = x2 * c + x1 * s;
    }
}

// ---------------- Attention scores: per (b,h), 64x64 tiles, scale + causal mask ----------------
__global__ __launch_bounds__(256)
void score_kernel(const float* __restrict__ Q, const float* __restrict__ K,
                  float* __restrict__ Sc)
{
    int bh = blockIdx.z;
    int b = bh >> 5, hh = bh & 31;
    int qi0 = blockIdx.y * 64, kj0 = blockIdx.x * 64;
    __shared__ float As[16][64];   // [kd][qi]
    __shared__ float Bs[16][64];   // [kd][kj]
    int tid = threadIdx.x;
    int tx = tid & 15, ty = tid >> 4;
    float acc[4][4] = {};
    const float* Qb = Q + ((size_t)b * SEQ + qi0) * DLLM + hh * HD;
    const float* Kb = K + ((size_t)b * SEQ + kj0) * DLLM + hh * HD;
    int r  = tid >> 2;
    int c4 = (tid & 3) * 4;
    for (int k0 = 0; k0 < HD; k0 += 16) {
        float4 qa = *(const float4*)(Qb + (size_t)r * DLLM + k0 + c4);
        As[c4+0][r] = qa.x; As[c4+1][r] = qa.y; As[c4+2][r] = qa.z; As[c4+3][r] = qa.w;
        float4 ka = *(const float4*)(Kb + (size_t)r * DLLM + k0 + c4);
        Bs[c4+0][r] = ka.x; Bs[c4+1][r] = ka.y; Bs[c4+2][r] = ka.z; Bs[c4+3][r] = ka.w;
        __syncthreads();
        #pragma unroll
        for (int kk = 0; kk < 16; kk++) {
            float a[4], bb[4];
            *(float4*)a  = *(const float4*)&As[kk][ty * 4];
            *(float4*)bb = *(const float4*)&Bs[kk][tx * 4];
            #pragma unroll
            for (int i = 0; i < 4; i++)
                #pragma unroll
                for (int j = 0; j < 4; j++)
                    acc[i][j] = fmaf(a[i], bb[j], acc[i][j]);
        }
        __syncthreads();
    }
    const float scale = 0.08838834764831845f;  // 1/sqrt(128)
    #pragma unroll
    for (int i = 0; i < 4; i++) {
        int qi = qi0 + ty * 4 + i;
        float* dst = Sc + ((size_t)bh * SEQ + qi) * SEQ + kj0 + tx * 4;
        #pragma unroll
        for (int j = 0; j < 4; j++) {
            int kj = kj0 + tx * 4 + j;
            dst[j] = (kj > qi) ? -1e30f : acc[i][j] * scale;
        }
    }
}

// ---------------- Row softmax (one block per row of 256) ----------------
__global__ __launch_bounds__(256)
void softmax_kernel(float* __restrict__ Sc)
{
    float* p = Sc + (size_t)blockIdx.x * SEQ;
    int tid = threadIdx.x;
    __shared__ float redm[8], reds[8];
    float v = p[tid];
    float m = v;
    #pragma unroll
    for (int o = 16; o; o >>= 1) m = fmaxf(m, __shfl_xor_sync(0xffffffffu, m, o));
    if ((tid & 31) == 0) redm[tid >> 5] = m;
    __syncthreads();
    if (tid < 32) {
        float x = (tid < 8) ? redm[tid] : -3.4e38f;
        #pragma unroll
        for (int o = 4; o; o >>= 1) x = fmaxf(x, __shfl_xor_sync(0xffffffffu, x, o));
        if (tid == 0) redm[0] = x;
    }
    __syncthreads();
    m = redm[0];
    float e = expf(v - m);
    float s = e;
    #pragma unroll
    for (int o = 16; o; o >>= 1) s += __shfl_xor_sync(0xffffffffu, s, o);
    if ((tid & 31) == 0) reds[tid >> 5] = s;
    __syncthreads();
    if (tid < 32) {
        float x = (tid < 8) ? reds[tid] : 0.f;
        #pragma unroll
        for (int o = 4; o; o >>= 1) x += __shfl_xor_sync(0xffffffffu, x, o);
        if (tid == 0) reds[0] = x;
    }
    __syncthreads();
    p[tid] = e / reds[0];
}

// ---------------- attn @ V : per (b,h), 64(rows) x 128(dims) tile ----------------
__global__ __launch_bounds__(256)
void av_kernel(const float* __restrict__ P, const float* __restrict__ V,
               float* __restrict__ O)
{
    int bh = blockIdx.y;
    int b = bh >> 5, hh = bh & 31;
    int qi0 = blockIdx.x * 64;
    __shared__ float Ps[16][64];    // [ki][qi]
    __shared__ float Vs[16][128];   // [ki][d]
    int tid = threadIdx.x;
    int tx = tid & 31, ty = tid >> 5;   // tx: 32 col-groups of 4, ty: 8 row-groups of 8
    float acc[8][4] = {};
    const float* Pb = P + ((size_t)bh * SEQ + qi0) * SEQ;
    const float* Vb = V + (size_t)b * SEQ * DLLM + hh * HD;
    int pq = tid >> 2, pk4 = (tid & 3) * 4;
    int vk = tid >> 4, vd8 = (tid & 15) * 8;
    for (int k0 = 0; k0 < SEQ; k0 += 16) {
        float4 pv = *(const float4*)(Pb + (size_t)pq * SEQ + k0 + pk4);
        Ps[pk4+0][pq] = pv.x; Ps[pk4+1][pq] = pv.y; Ps[pk4+2][pq] = pv.z; Ps[pk4+3][pq] = pv.w;
        const float* src = Vb + (size_t)(k0 + vk) * DLLM + vd8;
        *(float4*)&Vs[vk][vd8]     = *(const float4*)(src);
        *(float4*)&Vs[vk][vd8 + 4] = *(const float4*)(src + 4);
        __syncthreads();
        #pragma unroll
        for (int kk = 0; kk < 16; kk++) {
            float a[8], bb[4];
            *(float4*)(a)     = *(const float4*)&Ps[kk][ty * 8];
            *(float4*)(a + 4) = *(const float4*)&Ps[kk][ty * 8 + 4];
            *(float4*)bb      = *(const float4*)&Vs[kk][tx * 4];
            #pragma unroll
            for (int i = 0; i < 8; i++)
                #pragma unroll
                for (int j = 0; j < 4; j++)
                    acc[i][j] = fmaf(a[i], bb[j], acc[i][j]);
        }
        __syncthreads();
    }
    #pragma unroll
    for (int i = 0; i < 8; i++) {
        int qi = qi0 + ty * 8 + i;
        float* dst = O + ((size_t)b * SEQ + qi) * DLLM + hh * HD + tx * 4;
        *(float4*)dst = make_float4(acc[i][0], acc[i][1], acc[i][2], acc[i][3]);
    }
}

// ---------------- Mean pool over sequence ----------------
__global__ __launch_bounds__(256)
void pool_kernel(const float* __restrict__ x, float* __restrict__ pooled)
{
    int b = blockIdx.x;
    int d = blockIdx.y * 256 + threadIdx.x;
    float s = 0.f;
    const float* base = x + (size_t)b * SEQ * DLLM + d;
    for (int t = 0; t < SEQ; t++) s += base[(size_t)t * DLLM];
    pooled[(size_t)b * DLLM + d] = s * (1.f / SEQ);
}

// ---------------- Output head ----------------
__global__ __launch_bounds__(256)
void out1_kernel(const float* __restrict__ pooled, const float* __restrict__ W,
                 const float* __restrict__ bias, float* __restrict__ y1)
{
    int b = blockIdx.x;
    int n = blockIdx.y * 256 + threadIdx.x;
    const float* pv = pooled + (size_t)b * DLLM;
    float acc = bias[n];
    for (int k = 0; k < DLLM; k++)
        acc = fmaf(pv[k], W[(size_t)k * 768 + n], acc);
    y1[(size_t)b * 768 + n] = acc;
}

__global__ __launch_bounds__(256)
void out2_kernel(const float* __restrict__ y1, const float* __restrict__ W2,
                 const float* __restrict__ b2, float* __restrict__ out)
{
    int b = blockIdx.x;
    int tid = threadIdx.x;
    __shared__ float red[8];
    float s = 0.f;
    for (int j = tid; j < 768; j += 256) s += y1[(size_t)b * 768 + j] * W2[j];
    #pragma unroll
    for (int o = 16; o; o >>= 1) s += __shfl_xor_sync(0xffffffffu, s, o);
    if ((tid & 31) == 0) red[tid >> 5] = s;
    __syncthreads();
    if (tid < 32) {
        float x = (tid < 8) ? red[tid] : 0.f;
        #pragma unroll
        for (int o = 4; o; o >>= 1) x += __shfl_xor_sync(0xffffffffu, x, o);
        if (tid == 0) out[b] = x + b2[0];
    }
}

// ---------------- Host orchestration ----------------
extern "C" void kernel_launch(void* const* d_in, const int* in_sizes, int n_in,
                              void* d_out, int out_size)
{
    const float* text    = (const float*)d_in[0];
    const float* vision  = (const float*)d_in[1];
    const int*   prompt  = (const int*)  d_in[2];
    const float* in_W    = (const float*)d_in[3];
    const float* in_b    = (const float*)d_in[4];
    const float* table   = (const float*)d_in[5];
    const float* Wq      = (const float*)d_in[6];
    const float* Wk      = (const float*)d_in[7];
    const float* Wv      = (const float*)d_in[8];
    const float* Wo      = (const float*)d_in[9];
    const float* ln1     = (const float*)d_in[10];
    const float* ln2     = (const float*)d_in[11];
    const float* Wg      = (const float*)d_in[12];
    const float* Wu      = (const float*)d_in[13];
    const float* Wd      = (const float*)d_in[14];
    const float* final_w = (const float*)d_in[15];
    const float* out1W   = (const float*)d_in[16];
    const float* out1b   = (const float*)d_in[17];
    const float* out2W   = (const float*)d_in[18];
    const float* out2b   = (const float*)d_in[19];
    float* out = (float*)d_out;

    float *h, *x, *q, *k, *v, *o, *sc, *ff, *pooled, *y1;
    cudaGetSymbolAddress((void**)&h,  g_h);
    cudaGetSymbolAddress((void**)&x,  g_x);
    cudaGetSymbolAddress((void**)&q,  g_q);
    cudaGetSymbolAddress((void**)&k,  g_k);
    cudaGetSymbolAddress((void**)&v,  g_v);
    cudaGetSymbolAddress((void**)&o,  g_o);
    cudaGetSymbolAddress((void**)&sc, g_sc);
    cudaGetSymbolAddress((void**)&ff, g_ff);
    cudaGetSymbolAddress((void**)&pooled, g_pool);
    cudaGetSymbolAddress((void**)&y1, g_y1);

    // ---- Input embeddings into concatenated h: [prompt(128) | text(64) | vision(64)] ----
    embed_kernel<<<B * S_P, 256>>>(prompt, table, h);
    // text:  M = B*S_T = 512, remap rows b*64+t -> b*256 + 128 + t
    sgemm_kernel<0><<<dim3(DLLM/128, (B*S_T)/128), 256>>>(
        B*S_T, DLLM, DMODEL, text,   in_W, in_b, h, S_T, SEQ, S_P);
    // vision: rows b*64+t -> b*256 + 192 + t
    sgemm_kernel<0><<<dim3(DLLM/128, (B*S_V)/128), 256>>>(
        B*S_V, DLLM, DMODEL, vision, in_W, in_b, h, S_V, SEQ, S_P + S_T);

    for (int l = 0; l < NLAYER; l++) {
        const float* wq = Wq + (size_t)l * DLLM * DLLM;
        const float* wk = Wk + (size_t)l * DLLM * DLLM;
        const float* wv = Wv + (size_t)l * DLLM * DLLM;
        const float* wo = Wo + (size_t)l * DLLM * DLLM;
        const float* wg = Wg + (size_t)l * DLLM * DFF;
        const float* wu = Wu + (size_t)l * DLLM * DFF;
        const float* wd = Wd + (size_t)l * DFF * DLLM;
        const float* l1 = ln1 + (size_t)l * DLLM;
        const float* l2 = ln2 + (size_t)l * DLLM;

        // --- attention block ---
        rmsnorm_kernel<<<NTOK, 256>>>(h, l1, x);
        sgemm_kernel<0><<<dim3(DLLM/128, NTOK/128), 256>>>(NTOK, DLLM, DLLM, x, wq, nullptr, q, NTOK, NTOK, 0);
        sgemm_kernel<0><<<dim3(DLLM/128, NTOK/128), 256>>>(NTOK, DLLM, DLLM, x, wk, nullptr, k, NTOK, NTOK, 0);
        sgemm_kernel<0><<<dim3(DLLM/128, NTOK/128), 256>>>(NTOK, DLLM, DLLM, x, wv, nullptr, v, NTOK, NTOK, 0);
        rope_kernel<<<NTOK, 256>>>(q, k);
        score_kernel<<<dim3(SEQ/64, SEQ/64, B*NH), 256>>>(q, k, sc);
        softmax_kernel<<<B*NH*SEQ, 256>>>(sc);
        av_kernel<<<dim3(SEQ/64, B*NH), 256>>>(sc, v, o);
        sgemm_kernel<1><<<dim3(DLLM/128, NTOK/128), 256>>>(NTOK, DLLM, DLLM, o, wo, nullptr, h, NTOK, NTOK, 0);

        // --- FFN block (SwiGLU) ---
        rmsnorm_kernel<<<NTOK, 256>>>(h, l2, x);
        sgemm_kernel<0><<<dim3(DFF/128, NTOK/128), 256>>>(NTOK, DFF, DLLM, x, wg, nullptr, ff, NTOK, NTOK, 0);
        sgemm_kernel<2><<<dim3(DFF/128, NTOK/128), 256>>>(NTOK, DFF, DLLM, x, wu, nullptr, ff, NTOK, NTOK, 0);
        sgemm_kernel<1><<<dim3(DLLM/128, NTOK/128), 256>>>(NTOK, DLLM, DFF, ff, wd, nullptr, h, NTOK, NTOK, 0);
    }

    // ---- final norm, pool, output head ----
    rmsnorm_kernel<<<NTOK, 256>>>(h, final_w, x);
    pool_kernel<<<dim3(B, DLLM/256), 256>>>(x, pooled);
    out1_kernel<<<dim3(B, 768/256), 256>>>(pooled, out1W, out1b, y1);
    out2_kernel<<<B, 256>>>(y1, out2W, out2b, out);
}

// round 6
// speedup vs baseline: 1.0001x; 1.0001x over previous
#include <cuda_runtime.h>
#include <cuda_bf16.h>
#include <math.h>

// ---------------- Problem constants ----------------
#define B      8
#define S_P    128
#define S_T    64
#define S_V    64
#define SEQ    256          // S_P + S_T + S_V
#define DMODEL 768
#define DLLM   4096
#define NH     32
#define HD     128
#define DFF    11008
#define NLAYER 2
#define NTOK   (B*SEQ)      // 2048
#define EPSRMS 1e-5f

// ---------------- Scratch (device globals; no allocation allowed) ----------------
__device__ float g_h [NTOK*DLLM];                 // residual stream
__device__ float g_x [NTOK*DLLM];                 // normed activations
__device__ float g_q [NTOK*DLLM];
__device__ float g_k [NTOK*DLLM];
__device__ float g_v [NTOK*DLLM];
__device__ float g_o [NTOK*DLLM];
__device__ float g_sc[B*NH*SEQ*SEQ];              // attention scores / probs
__device__ float g_ff[NTOK*DFF];                  // FFN gate / fused buffer
__device__ float g_pool[B*DLLM];
__device__ float g_y1[B*768];

__device__ __forceinline__ float siluf(float x) { return x / (1.f + expf(-x)); }

// ---------------- Generic tiled SGEMM ----------------
// C[M,N] (+)= A[M,K] @ B[K,N] (+bias), row-major everywhere.
// Row remap for scattering into the concatenated sequence:
//   orow = (r / rpbi) * rpbo + roff + (r % rpbi)
// EPI: 0 = store, 1 = C += acc, 2 = C = silu(C_old) * acc   (SwiGLU fuse)
template<int EPI>
__global__ __launch_bounds__(256)
void sgemm_kernel(int M, int N, int K,
                  const float* __restrict__ A,
                  const float* __restrict__ Bm,
                  const float* __restrict__ bias,
                  float* __restrict__ C,
                  int rpbi, int rpbo, int roff)
{
    __shared__ float As[8][128];   // [k][m]  (transposed on load)
    __shared__ float Bs[8][128];   // [k][n]

    const int bx = blockIdx.x;     // N tile
    const int by = blockIdx.y;     // M tile
    const int tid = threadIdx.x;
    const int tx = tid & 15;       // 0..15 -> 8 cols each
    const int ty = tid >> 4;       // 0..15 -> 8 rows each

    const int aRow = tid >> 1;            // 0..127
    const int aCol = (tid & 1) * 4;       // 0 or 4
    const int bRow = tid >> 5;            // 0..7
    const int bCol = (tid & 31) * 4;      // 0..124

    const float* Ab = A + (size_t)(by * 128) * K;
    const float* Bb = Bm + (size_t)(bx * 128);

    float acc[8][8];
    #pragma unroll
    for (int i = 0; i < 8; i++)
        #pragma unroll
        for (int j = 0; j < 8; j++) acc[i][j] = 0.f;

    for (int k0 = 0; k0 < K; k0 += 8) {
        // Load A tile (transpose into As[k][m])
        float4 av = *(const float4*)(Ab + (size_t)aRow * K + k0 + aCol);
        As[aCol + 0][aRow] = av.x;
        As[aCol + 1][aRow] = av.y;
        As[aCol + 2][aRow] = av.z;
        As[aCol + 3][aRow] = av.w;
        // Load B tile
        float4 bv = *(const float4*)(Bb + (size_t)(k0 + bRow) * N + bCol);
        *(float4*)&Bs[bRow][bCol] = bv;
        __syncthreads();

        #pragma unroll
        for (int kk = 0; kk < 8; kk++) {
            float a[8], b[8];
            *(float4*)(a)     = *(const float4*)&As[kk][ty * 8];
            *(float4*)(a + 4) = *(const float4*)&As[kk][ty * 8 + 4];
            *(float4*)(b)     = *(const float4*)&Bs[kk][tx * 8];
            *(float4*)(b + 4) = *(const float4*)&Bs[kk][tx * 8 + 4];
            #pragma unroll
            for (int i = 0; i < 8; i++)
                #pragma unroll
                for (int j = 0; j < 8; j++)
                    acc[i][j] = fmaf(a[i], b[j], acc[i][j]);
        }
        __syncthreads();
    }

    const int col0 = bx * 128 + tx * 8;
    float bseg[8];
    if (bias) {
        *(float4*)(bseg)     = *(const float4*)(bias + col0);
        *(float4*)(bseg + 4) = *(const float4*)(bias + col0 + 4);
    } else {
        #pragma unroll
        for (int j = 0; j < 8; j++) bseg[j] = 0.f;
    }

    #pragma unroll
    for (int i = 0; i < 8; i++) {
        int r = by * 128 + ty * 8 + i;
        int orow = (r / rpbi) * rpbo + roff + (r % rpbi);
        float* dst = C + (size_t)orow * N + col0;
        #pragma unroll
        for (int half = 0; half < 2; half++) {
            float4 val = make_float4(acc[i][half*4+0] + bseg[half*4+0],
                                     acc[i][half*4+1] + bseg[half*4+1],
                                     acc[i][half*4+2] + bseg[half*4+2],
                                     acc[i][half*4+3] + bseg[half*4+3]);
            if (EPI == 0) {
                *(float4*)(dst + half*4) = val;
            } else if (EPI == 1) {
                float4 c = *(float4*)(dst + half*4);
                c.x += val.x; c.y += val.y; c.z += val.z; c.w += val.w;
                *(float4*)(dst + half*4) = c;
            } else {
                float4 gte = *(float4*)(dst + half*4);   // gate values
                gte.x = siluf(gte.x) * val.x;
                gte.y = siluf(gte.y) * val.y;
                gte.z = siluf(gte.z) * val.z;
                gte.w = siluf(gte.w) * val.w;
                *(float4*)(dst + half*4) = gte;
            }
        }
    }
}

// ---------------- Embedding gather (prompt ids) ----------------
__global__ __launch_bounds__(256)
void embed_kernel(const int* __restrict__ ids, const float* __restrict__ table,
                  float* __restrict__ h)
{
    int t = blockIdx.x;                 // 0..B*S_P-1
    int b = t >> 7, p = t & 127;
    int id = ids[t];
    const float4* src = (const float4*)(table + (size_t)id * DLLM);
    float4* dst = (float4*)(h + ((size_t)b * SEQ + p) * DLLM);
    for (int i = threadIdx.x; i < DLLM / 4; i += 256) dst[i] = src[i];
}

// ---------------- RMSNorm (one block per token) ----------------
__global__ __launch_bounds__(256)
void rmsnorm_kernel(const float* __restrict__ in, const float* __restrict__ w,
                    float* __restrict__ out)
{
    size_t t = blockIdx.x;
    const float4* xp = (const float4*)(in + t * DLLM);
    __shared__ float red[8];
    float ss = 0.f;
    for (int i = threadIdx.x; i < DLLM / 4; i += 256) {
        float4 v = xp[i];
        ss += v.x*v.x + v.y*v.y + v.z*v.z + v.w*v.w;
    }
    #pragma unroll
    for (int o = 16; o; o >>= 1) ss += __shfl_xor_sync(0xffffffffu, ss, o);
    if ((threadIdx.x & 31) == 0) red[threadIdx.x >> 5] = ss;
    __syncthreads();
    if (threadIdx.x < 32) {
        float v = (threadIdx.x < 8) ? red[threadIdx.x] : 0.f;
        #pragma unroll
        for (int o = 4; o; o >>= 1) v += __shfl_xor_sync(0xffffffffu, v, o);
        if (threadIdx.x == 0) red[0] = v;
    }
    __syncthreads();
    float r = rsqrtf(red[0] / (float)DLLM + EPSRMS);
    const float4* wp = (const float4*)w;
    float4* op = (float4*)(out + t * DLLM);
    for (int i = threadIdx.x; i < DLLM / 4; i += 256) {
        float4 v = xp[i], wv = wp[i];
        op[i] = make_float4(v.x*r*wv.x, v.y*r*wv.y, v.z*r*wv.z, v.w*r*wv.w);
    }
}

// ---------------- RoPE (HF layout) applied in-place to q and k ----------------
__global__ __launch_bounds__(256)
void rope_kernel(float* __restrict__ q, float* __restrict__ k)
{
    int t = blockIdx.x;                  // token 0..NTOK-1
    int pos = t & (SEQ - 1);             // position within sequence
    const float LOG_THETA = 9.210340371976184f;  // ln(10000)
    for (int it = 0; it < 8; it++) {
        int p = threadIdx.x + it * 256;  // 0..2047 = (h, j)
        int hh = p >> 6, j = p & 63;
        float inv_freq = expf(-(float)j * (LOG_THETA / 64.f));
        float ang = (float)pos * inv_freq;
        float c = cosf(ang), s = sinf(ang);
        size_t base = (size_t)t * DLLM + hh * HD + j;
        float x1 = q[base], x2 = q[base + 64];
        q[base]      = x1 * c - x2 * s;
        q[base + 64] = x2 * c + x1 * s;
        x1 = k[base]; x2 = k[base + 64];
        k[base]      = x1 * c - x2 * s;
        k[base + 64] = x2 * c + x1 * s;
    }
}

// ---------------- Attention scores: per (b,h), 64x64 tiles, scale + causal mask ----------------
__global__ __launch_bounds__(256)
void score_kernel(const float* __restrict__ Q, const float* __restrict__ K,
                  float* __restrict__ Sc)
{
    int bh = blockIdx.z;
    int b = bh >> 5, hh = bh & 31;
    int qi0 = blockIdx.y * 64, kj0 = blockIdx.x * 64;
    __shared__ float As[16][64];   // [kd][qi]
    __shared__ float Bs[16][64];   // [kd][kj]
    int tid = threadIdx.x;
    int tx = tid & 15, ty = tid >> 4;
    float acc[4][4] = {};
    const float* Qb = Q + ((size_t)b * SEQ + qi0) * DLLM + hh * HD;
    const float* Kb = K + ((size_t)b * SEQ + kj0) * DLLM + hh * HD;
    int r  = tid >> 2;
    int c4 = (tid & 3) * 4;
    for (int k0 = 0; k0 < HD; k0 += 16) {
        float4 qa = *(const float4*)(Qb + (size_t)r * DLLM + k0 + c4);
        As[c4+0][r] = qa.x; As[c4+1][r] = qa.y; As[c4+2][r] = qa.z; As[c4+3][r] = qa.w;
        float4 ka = *(const float4*)(Kb + (size_t)r * DLLM + k0 + c4);
        Bs[c4+0][r] = ka.x; Bs[c4+1][r] = ka.y; Bs[c4+2][r] = ka.z; Bs[c4+3][r] = ka.w;
        __syncthreads();
        #pragma unroll
        for (int kk = 0; kk < 16; kk++) {
            float a[4], bb[4];
            *(float4*)a  = *(const float4*)&As[kk][ty * 4];
            *(float4*)bb = *(const float4*)&Bs[kk][tx * 4];
            #pragma unroll
            for (int i = 0; i < 4; i++)
                #pragma unroll
                for (int j = 0; j < 4; j++)
                    acc[i][j] = fmaf(a[i], bb[j], acc[i][j]);
        }
        __syncthreads();
    }
    const float scale = 0.08838834764831845f;  // 1/sqrt(128)
    #pragma unroll
    for (int i = 0; i < 4; i++) {
        int qi = qi0 + ty * 4 + i;
        float* dst = Sc + ((size_t)bh * SEQ + qi) * SEQ + kj0 + tx * 4;
        #pragma unroll
        for (int j = 0; j < 4; j++) {
            int kj = kj0 + tx * 4 + j;
            dst[j] = (kj > qi) ? -1e30f : acc[i][j] * scale;
        }
    }
}

// ---------------- Row softmax (one block per row of 256) ----------------
__global__ __launch_bounds__(256)
void softmax_kernel(float* __restrict__ Sc)
{
    float* p = Sc + (size_t)blockIdx.x * SEQ;
    int tid = threadIdx.x;
    __shared__ float redm[8], reds[8];
    float v = p[tid];
    float m = v;
    #pragma unroll
    for (int o = 16; o; o >>= 1) m = fmaxf(m, __shfl_xor_sync(0xffffffffu, m, o));
    if ((tid & 31) == 0) redm[tid >> 5] = m;
    __syncthreads();
    if (tid < 32) {
        float x = (tid < 8) ? redm[tid] : -3.4e38f;
        #pragma unroll
        for (int o = 4; o; o >>= 1) x = fmaxf(x, __shfl_xor_sync(0xffffffffu, x, o));
        if (tid == 0) redm[0] = x;
    }
    __syncthreads();
    m = redm[0];
    float e = expf(v - m);
    float s = e;
    #pragma unroll
    for (int o = 16; o; o >>= 1) s += __shfl_xor_sync(0xffffffffu, s, o);
    if ((tid & 31) == 0) reds[tid >> 5] = s;
    __syncthreads();
    if (tid < 32) {
        float x = (tid < 8) ? reds[tid] : 0.f;
        #pragma unroll
        for (int o = 4; o; o >>= 1) x += __shfl_xor_sync(0xffffffffu, x, o);
        if (tid == 0) reds[0] = x;
    }
    __syncthreads();
    p[tid] = e / reds[0];
}

// ---------------- attn @ V : per (b,h), 64(rows) x 128(dims) tile ----------------
__global__ __launch_bounds__(256)
void av_kernel(const float* __restrict__ P, const float* __restrict__ V,
               float* __restrict__ O)
{
    int bh = blockIdx.y;
    int b = bh >> 5, hh = bh & 31;
    int qi0 = blockIdx.x * 64;
    __shared__ float Ps[16][64];    // [ki][qi]
    __shared__ float Vs[16][128];   // [ki][d]
    int tid = threadIdx.x;
    int tx = tid & 31, ty = tid >> 5;   // tx: 32 col-groups of 4, ty: 8 row-groups of 8
    float acc[8][4] = {};
    const float* Pb = P + ((size_t)bh * SEQ + qi0) * SEQ;
    const float* Vb = V + (size_t)b * SEQ * DLLM + hh * HD;
    int pq = tid >> 2, pk4 = (tid & 3) * 4;
    int vk = tid >> 4, vd8 = (tid & 15) * 8;
    for (int k0 = 0; k0 < SEQ; k0 += 16) {
        float4 pv = *(const float4*)(Pb + (size_t)pq * SEQ + k0 + pk4);
        Ps[pk4+0][pq] = pv.x; Ps[pk4+1][pq] = pv.y; Ps[pk4+2][pq] = pv.z; Ps[pk4+3][pq] = pv.w;
        const float* src = Vb + (size_t)(k0 + vk) * DLLM + vd8;
        *(float4*)&Vs[vk][vd8]     = *(const float4*)(src);
        *(float4*)&Vs[vk][vd8 + 4] = *(const float4*)(src + 4);
        __syncthreads();
        #pragma unroll
        for (int kk = 0; kk < 16; kk++) {
            float a[8], bb[4];
            *(float4*)(a)     = *(const float4*)&Ps[kk][ty * 8];
            *(float4*)(a + 4) = *(const float4*)&Ps[kk][ty * 8 + 4];
            *(float4*)bb      = *(const float4*)&Vs[kk][tx * 4];
            #pragma unroll
            for (int i = 0; i < 8; i++)
                #pragma unroll
                for (int j = 0; j < 4; j++)
                    acc[i][j] = fmaf(a[i], bb[j], acc[i][j]);
        }
        __syncthreads();
    }
    #pragma unroll
    for (int i = 0; i < 8; i++) {
        int qi = qi0 + ty * 8 + i;
        float* dst = O + ((size_t)b * SEQ + qi) * DLLM + hh * HD + tx * 4;
        *(float4*)dst = make_float4(acc[i][0], acc[i][1], acc[i][2], acc[i][3]);
    }
}

// ---------------- Mean pool over sequence ----------------
__global__ __launch_bounds__(256)
void pool_kernel(const float* __restrict__ x, float* __restrict__ pooled)
{
    int b = blockIdx.x;
    int d = blockIdx.y * 256 + threadIdx.x;
    float s = 0.f;
    const float* base = x + (size_t)b * SEQ * DLLM + d;
    for (int t = 0; t < SEQ; t++) s += base[(size_t)t * DLLM];
    pooled[(size_t)b * DLLM + d] = s * (1.f / SEQ);
}

// ---------------- Output head ----------------
__global__ __launch_bounds__(256)
void out1_kernel(const float* __restrict__ pooled, const float* __restrict__ W,
                 const float* __restrict__ bias, float* __restrict__ y1)
{
    int b = blockIdx.x;
    int n = blockIdx.y * 256 + threadIdx.x;
    const float* pv = pooled + (size_t)b * DLLM;
    float acc = bias[n];
    for (int k = 0; k < DLLM; k++)
        acc = fmaf(pv[k], W[(size_t)k * 768 + n], acc);
    y1[(size_t)b * 768 + n] = acc;
}

__global__ __launch_bounds__(256)
void out2_kernel(const float* __restrict__ y1, const float* __restrict__ W2,
                 const float* __restrict__ b2, float* __restrict__ out)
{
    int b = blockIdx.x;
    int tid = threadIdx.x;
    __shared__ float red[8];
    float s = 0.f;
    for (int j = tid; j < 768; j += 256) s += y1[(size_t)b * 768 + j] * W2[j];
    #pragma unroll
    for (int o = 16; o; o >>= 1) s += __shfl_xor_sync(0xffffffffu, s, o);
    if ((tid & 31) == 0) red[tid >> 5] = s;
    __syncthreads();
    if (tid < 32) {
        float x = (tid < 8) ? red[tid] : 0.f;
        #pragma unroll
        for (int o = 4; o; o >>= 1) x += __shfl_xor_sync(0xffffffffu, x, o);
        if (tid == 0) out[b] = x + b2[0];
    }
}

// ---------------- Host orchestration ----------------
extern "C" void kernel_launch(void* const* d_in, const int* in_sizes, int n_in,
                              void* d_out, int out_size)
{
    const float* text    = (const float*)d_in[0];
    const float* vision  = (const float*)d_in[1];
    const int*   prompt  = (const int*)  d_in[2];
    const float* in_W    = (const float*)d_in[3];
    const float* in_b    = (const float*)d_in[4];
    const float* table   = (const float*)d_in[5];
    const float* Wq      = (const float*)d_in[6];
    const float* Wk      = (const float*)d_in[7];
    const float* Wv      = (const float*)d_in[8];
    const float* Wo      = (const float*)d_in[9];
    const float* ln1     = (const float*)d_in[10];
    const float* ln2     = (const float*)d_in[11];
    const float* Wg      = (const float*)d_in[12];
    const float* Wu      = (const float*)d_in[13];
    const float* Wd      = (const float*)d_in[14];
    const float* final_w = (const float*)d_in[15];
    const float* out1W   = (const float*)d_in[16];
    const float* out1b   = (const float*)d_in[17];
    const float* out2W   = (const float*)d_in[18];
    const float* out2b   = (const float*)d_in[19];
    float* out = (float*)d_out;

    float *h, *x, *q, *k, *v, *o, *sc, *ff, *pooled, *y1;
    cudaGetSymbolAddress((void**)&h,  g_h);
    cudaGetSymbolAddress((void**)&x,  g_x);
    cudaGetSymbolAddress((void**)&q,  g_q);
    cudaGetSymbolAddress((void**)&k,  g_k);
    cudaGetSymbolAddress((void**)&v,  g_v);
    cudaGetSymbolAddress((void**)&o,  g_o);
    cudaGetSymbolAddress((void**)&sc, g_sc);
    cudaGetSymbolAddress((void**)&ff, g_ff);
    cudaGetSymbolAddress((void**)&pooled, g_pool);
    cudaGetSymbolAddress((void**)&y1, g_y1);

    // ---- Input embeddings into concatenated h: [prompt(128) | text(64) | vision(64)] ----
    embed_kernel<<<B * S_P, 256>>>(prompt, table, h);
    // text:  M = B*S_T = 512, remap rows b*64+t -> b*256 + 128 + t
    sgemm_kernel<0><<<dim3(DLLM/128, (B*S_T)/128), 256>>>(
        B*S_T, DLLM, DMODEL, text,   in_W, in_b, h, S_T, SEQ, S_P);
    // vision: rows b*64+t -> b*256 + 192 + t
    sgemm_kernel<0><<<dim3(DLLM/128, (B*S_V)/128), 256>>>(
        B*S_V, DLLM, DMODEL, vision, in_W, in_b, h, S_V, SEQ, S_P + S_T);

    for (int l = 0; l < NLAYER; l++) {
        const float* wq = Wq + (size_t)l * DLLM * DLLM;
        const float* wk = Wk + (size_t)l * DLLM * DLLM;
        const float* wv = Wv + (size_t)l * DLLM * DLLM;
        const float* wo = Wo + (size_t)l * DLLM * DLLM;
        const float* wg = Wg + (size_t)l * DLLM * DFF;
        const float* wu = Wu + (size_t)l * DLLM * DFF;
        const float* wd = Wd + (size_t)l * DFF * DLLM;
        const float* l1 = ln1 + (size_t)l * DLLM;
        const float* l2 = ln2 + (size_t)l * DLLM;

        // --- attention block ---
        rmsnorm_kernel<<<NTOK, 256>>>(h, l1, x);
        sgemm_kernel<0><<<dim3(DLLM/128, NTOK/128), 256>>>(NTOK, DLLM, DLLM, x, wq, nullptr, q, NTOK, NTOK, 0);
        sgemm_kernel<0><<<dim3(DLLM/128, NTOK/128), 256>>>(NTOK, DLLM, DLLM, x, wk, nullptr, k, NTOK, NTOK, 0);
        sgemm_kernel<0><<<dim3(DLLM/128, NTOK/128), 256>>>(NTOK, DLLM, DLLM, x, wv, nullptr, v, NTOK, NTOK, 0);
        rope_kernel<<<NTOK, 256>>>(q, k);
        score_kernel<<<dim3(SEQ/64, SEQ/64, B*NH), 256>>>(q, k, sc);
        softmax_kernel<<<B*NH*SEQ, 256>>>(sc);
        av_kernel<<<dim3(SEQ/64, B*NH), 256>>>(sc, v, o);
        sgemm_kernel<1><<<dim3(DLLM/128, NTOK/128), 256>>>(NTOK, DLLM, DLLM, o, wo, nullptr, h, NTOK, NTOK, 0);

        // --- FFN block (SwiGLU) ---
        rmsnorm_kernel<<<NTOK, 256>>>(h, l2, x);
        sgemm_kernel<0><<<dim3(DFF/128, NTOK/128), 256>>>(NTOK, DFF, DLLM, x, wg, nullptr, ff, NTOK, NTOK, 0);
        sgemm_kernel<2><<<dim3(DFF/128, NTOK/128), 256>>>(NTOK, DFF, DLLM, x, wu, nullptr, ff, NTOK, NTOK, 0);
        sgemm_kernel<1><<<dim3(DLLM/128, NTOK/128), 256>>>(NTOK, DLLM, DFF, ff, wd, nullptr, h, NTOK, NTOK, 0);
    }

    // ---- final norm, pool, output head ----
    rmsnorm_kernel<<<NTOK, 256>>>(h, final_w, x);
    pool_kernel<<<dim3(B, DLLM/256), 256>>>(x, pooled);
    out1_kernel<<<dim3(B, 768/256), 256>>>(pooled, out1W, out1b, y1);
    out2_kernel<<<B, 256>>>(y1, out2W, out2b, out);
}

// round 7
// speedup vs baseline: 1.0008x; 1.0008x over previous
#include <cuda_runtime.h>
#include <cuda_bf16.h>
#include <math.h>

// ---------------- Problem constants ----------------
#define B      8
#define S_P    128
#define S_T    64
#define S_V    64
#define SEQ    256          // S_P + S_T + S_V
#define DMODEL 768
#define DLLM   4096
#define NH     32
#define HD     128
#define DFF    11008
#define NLAYER 2
#define NTOK   (B*SEQ)      // 2048
#define EPSRMS 1e-5f

// ---------------- Scratch (device globals; no allocation allowed) ----------------
__device__ float g_h [NTOK*DLLM];                 // residual stream
__device__ float g_x [NTOK*DLLM];                 // normed activations
__device__ float g_q [NTOK*DLLM];
__device__ float g_k [NTOK*DLLM];
__device__ float g_v [NTOK*DLLM];
__device__ float g_o [NTOK*DLLM];
__device__ float g_sc[B*NH*SEQ*SEQ];              // attention scores / probs
__device__ float g_ff[NTOK*DFF];                  // FFN gate / fused buffer
__device__ float g_pool[B*DLLM];
__device__ float g_y1[B*768];

__device__ __forceinline__ float siluf(float x) { return x / (1.f + expf(-x)); }

// ---------------- Generic tiled SGEMM ----------------
// C[M,N] (+)= A[M,K] @ B[K,N] (+bias), row-major everywhere.
// Row remap for scattering into the concatenated sequence:
//   orow = (r / rpbi) * rpbo + roff + (r % rpbi)
// EPI: 0 = store, 1 = C += acc, 2 = C = silu(C_old) * acc   (SwiGLU fuse)
template<int EPI>
__global__ __launch_bounds__(256)
void sgemm_kernel(int M, int N, int K,
                  const float* __restrict__ A,
                  const float* __restrict__ Bm,
                  const float* __restrict__ bias,
                  float* __restrict__ C,
                  int rpbi, int rpbo, int roff)
{
    __shared__ float As[8][128];   // [k][m]  (transposed on load)
    __shared__ float Bs[8][128];   // [k][n]

    const int bx = blockIdx.x;     // N tile
    const int by = blockIdx.y;     // M tile
    const int tid = threadIdx.x;
    const int tx = tid & 15;       // 0..15 -> 8 cols each
    const int ty = tid >> 4;       // 0..15 -> 8 rows each

    const int aRow = tid >> 1;            // 0..127
    const int aCol = (tid & 1) * 4;       // 0 or 4
    const int bRow = tid >> 5;            // 0..7
    const int bCol = (tid & 31) * 4;      // 0..124

    const float* Ab = A + (size_t)(by * 128) * K;
    const float* Bb = Bm + (size_t)(bx * 128);

    float acc[8][8];
    #pragma unroll
    for (int i = 0; i < 8; i++)
        #pragma unroll
        for (int j = 0; j < 8; j++) acc[i][j] = 0.f;

    for (int k0 = 0; k0 < K; k0 += 8) {
        // Load A tile (transpose into As[k][m])
        float4 av = *(const float4*)(Ab + (size_t)aRow * K + k0 + aCol);
        As[aCol + 0][aRow] = av.x;
        As[aCol + 1][aRow] = av.y;
        As[aCol + 2][aRow] = av.z;
        As[aCol + 3][aRow] = av.w;
        // Load B tile
        float4 bv = *(const float4*)(Bb + (size_t)(k0 + bRow) * N + bCol);
        *(float4*)&Bs[bRow][bCol] = bv;
        __syncthreads();

        #pragma unroll
        for (int kk = 0; kk < 8; kk++) {
            float a[8], b[8];
            *(float4*)(a)     = *(const float4*)&As[kk][ty * 8];
            *(float4*)(a + 4) = *(const float4*)&As[kk][ty * 8 + 4];
            *(float4*)(b)     = *(const float4*)&Bs[kk][tx * 8];
            *(float4*)(b + 4) = *(const float4*)&Bs[kk][tx * 8 + 4];
            #pragma unroll
            for (int i = 0; i < 8; i++)
                #pragma unroll
                for (int j = 0; j < 8; j++)
                    acc[i][j] = fmaf(a[i], b[j], acc[i][j]);
        }
        __syncthreads();
    }

    const int col0 = bx * 128 + tx * 8;
    float bseg[8];
    if (bias) {
        *(float4*)(bseg)     = *(const float4*)(bias + col0);
        *(float4*)(bseg + 4) = *(const float4*)(bias + col0 + 4);
    } else {
        #pragma unroll
        for (int j = 0; j < 8; j++) bseg[j] = 0.f;
    }

    #pragma unroll
    for (int i = 0; i < 8; i++) {
        int r = by * 128 + ty * 8 + i;
        int orow = (r / rpbi) * rpbo + roff + (r % rpbi);
        float* dst = C + (size_t)orow * N + col0;
        #pragma unroll
        for (int half = 0; half < 2; half++) {
            float4 val = make_float4(acc[i][half*4+0] + bseg[half*4+0],
                                     acc[i][half*4+1] + bseg[half*4+1],
                                     acc[i][half*4+2] + bseg[half*4+2],
                                     acc[i][half*4+3] + bseg[half*4+3]);
            if (EPI == 0) {
                *(float4*)(dst + half*4) = val;
            } else if (EPI == 1) {
                float4 c = *(float4*)(dst + half*4);
                c.x += val.x; c.y += val.y; c.z += val.z; c.w += val.w;
                *(float4*)(dst + half*4) = c;
            } else {
                float4 gte = *(float4*)(dst + half*4);   // gate values
                gte.x = siluf(gte.x) * val.x;
                gte.y = siluf(gte.y) * val.y;
                gte.z = siluf(gte.z) * val.z;
                gte.w = siluf(gte.w) * val.w;
                *(float4*)(dst + half*4) = gte;
            }
        }
    }
}

// ---------------- Embedding gather (prompt ids) ----------------
__global__ __launch_bounds__(256)
void embed_kernel(const int* __restrict__ ids, const float* __restrict__ table,
                  float* __restrict__ h)
{
    int t = blockIdx.x;                 // 0..B*S_P-1
    int b = t >> 7, p = t & 127;
    int id = ids[t];
    const float4* src = (const float4*)(table + (size_t)id * DLLM);
    float4* dst = (float4*)(h + ((size_t)b * SEQ + p) * DLLM);
    for (int i = threadIdx.x; i < DLLM / 4; i += 256) dst[i] = src[i];
}

// ---------------- RMSNorm (one block per token) ----------------
__global__ __launch_bounds__(256)
void rmsnorm_kernel(const float* __restrict__ in, const float* __restrict__ w,
                    float* __restrict__ out)
{
    size_t t = blockIdx.x;
    const float4* xp = (const float4*)(in + t * DLLM);
    __shared__ float red[8];
    float ss = 0.f;
    for (int i = threadIdx.x; i < DLLM / 4; i += 256) {
        float4 v = xp[i];
        ss += v.x*v.x + v.y*v.y + v.z*v.z + v.w*v.w;
    }
    #pragma unroll
    for (int o = 16; o; o >>= 1) ss += __shfl_xor_sync(0xffffffffu, ss, o);
    if ((threadIdx.x & 31) == 0) red[threadIdx.x >> 5] = ss;
    __syncthreads();
    if (threadIdx.x < 32) {
        float v = (threadIdx.x < 8) ? red[threadIdx.x] : 0.f;
        #pragma unroll
        for (int o = 4; o; o >>= 1) v += __shfl_xor_sync(0xffffffffu, v, o);
        if (threadIdx.x == 0) red[0] = v;
    }
    __syncthreads();
    float r = rsqrtf(red[0] / (float)DLLM + EPSRMS);
    const float4* wp = (const float4*)w;
    float4* op = (float4*)(out + t * DLLM);
    for (int i = threadIdx.x; i < DLLM / 4; i += 256) {
        float4 v = xp[i], wv = wp[i];
        op[i] = make_float4(v.x*r*wv.x, v.y*r*wv.y, v.z*r*wv.z, v.w*r*wv.w);
    }
}

// ---------------- RoPE (HF layout) applied in-place to q and k ----------------
__global__ __launch_bounds__(256)
void rope_kernel(float* __restrict__ q, float* __restrict__ k)
{
    int t = blockIdx.x;                  // token 0..NTOK-1
    int pos = t & (SEQ - 1);             // position within sequence
    const float LOG_THETA = 9.210340371976184f;  // ln(10000)
    for (int it = 0; it < 8; it++) {
        int p = threadIdx.x + it * 256;  // 0..2047 = (h, j)
        int hh = p >> 6, j = p & 63;
        float inv_freq = expf(-(float)j * (LOG_THETA / 64.f));
        float ang = (float)pos * inv_freq;
        float c = cosf(ang), s = sinf(ang);
        size_t base = (size_t)t * DLLM + hh * HD + j;
        float x1 = q[base], x2 = q[base + 64];
        q[base]      = x1 * c - x2 * s;
        q[base + 64] = x2 * c + x1 * s;
        x1 = k[base]; x2 = k[base + 64];
        k[base]      = x1 * c - x2 * s;
        k[base + 64] = x2 * c + x1 * s;
    }
}

// ---------------- Attention scores: per (b,h), 64x64 tiles, scale + causal mask ----------------
__global__ __launch_bounds__(256)
void score_kernel(const float* __restrict__ Q, const float* __restrict__ K,
                  float* __restrict__ Sc)
{
    int bh = blockIdx.z;
    int b = bh >> 5, hh = bh & 31;
    int qi0 = blockIdx.y * 64, kj0 = blockIdx.x * 64;
    __shared__ float As[16][64];   // [kd][qi]
    __shared__ float Bs[16][64];   // [kd][kj]
    int tid = threadIdx.x;
    int tx = tid & 15, ty = tid >> 4;
    float acc[4][4] = {};
    const float* Qb = Q + ((size_t)b * SEQ + qi0) * DLLM + hh * HD;
    const float* Kb = K + ((size_t)b * SEQ + kj0) * DLLM + hh * HD;
    int r  = tid >> 2;
    int c4 = (tid & 3) * 4;
    for (int k0 = 0; k0 < HD; k0 += 16) {
        float4 qa = *(const float4*)(Qb + (size_t)r * DLLM + k0 + c4);
        As[c4+0][r] = qa.x; As[c4+1][r] = qa.y; As[c4+2][r] = qa.z; As[c4+3][r] = qa.w;
        float4 ka = *(const float4*)(Kb + (size_t)r * DLLM + k0 + c4);
        Bs[c4+0][r] = ka.x; Bs[c4+1][r] = ka.y; Bs[c4+2][r] = ka.z; Bs[c4+3][r] = ka.w;
        __syncthreads();
        #pragma unroll
        for (int kk = 0; kk < 16; kk++) {
            float a[4], bb[4];
            *(float4*)a  = *(const float4*)&As[kk][ty * 4];
            *(float4*)bb = *(const float4*)&Bs[kk][tx * 4];
            #pragma unroll
            for (int i = 0; i < 4; i++)
                #pragma unroll
                for (int j = 0; j < 4; j++)
                    acc[i][j] = fmaf(a[i], bb[j], acc[i][j]);
        }
        __syncthreads();
    }
    const float scale = 0.08838834764831845f;  // 1/sqrt(128)
    #pragma unroll
    for (int i = 0; i < 4; i++) {
        int qi = qi0 + ty * 4 + i;
        float* dst = Sc + ((size_t)bh * SEQ + qi) * SEQ + kj0 + tx * 4;
        #pragma unroll
        for (int j = 0; j < 4; j++) {
            int kj = kj0 + tx * 4 + j;
            dst[j] = (kj > qi) ? -1e30f : acc[i][j] * scale;
        }
    }
}

// ---------------- Row softmax (one block per row of 256) ----------------
__global__ __launch_bounds__(256)
void softmax_kernel(float* __restrict__ Sc)
{
    float* p = Sc + (size_t)blockIdx.x * SEQ;
    int tid = threadIdx.x;
    __shared__ float redm[8], reds[8];
    float v = p[tid];
    float m = v;
    #pragma unroll
    for (int o = 16; o; o >>= 1) m = fmaxf(m, __shfl_xor_sync(0xffffffffu, m, o));
    if ((tid & 31) == 0) redm[tid >> 5] = m;
    __syncthreads();
    if (tid < 32) {
        float x = (tid < 8) ? redm[tid] : -3.4e38f;
        #pragma unroll
        for (int o = 4; o; o >>= 1) x = fmaxf(x, __shfl_xor_sync(0xffffffffu, x, o));
        if (tid == 0) redm[0] = x;
    }
    __syncthreads();
    m = redm[0];
    float e = expf(v - m);
    float s = e;
    #pragma unroll
    for (int o = 16; o; o >>= 1) s += __shfl_xor_sync(0xffffffffu, s, o);
    if ((tid & 31) == 0) reds[tid >> 5] = s;
    __syncthreads();
    if (tid < 32) {
        float x = (tid < 8) ? reds[tid] : 0.f;
        #pragma unroll
        for (int o = 4; o; o >>= 1) x += __shfl_xor_sync(0xffffffffu, x, o);
        if (tid == 0) reds[0] = x;
    }
    __syncthreads();
    p[tid] = e / reds[0];
}

// ---------------- attn @ V : per (b,h), 64(rows) x 128(dims) tile ----------------
__global__ __launch_bounds__(256)
void av_kernel(const float* __restrict__ P, const float* __restrict__ V,
               float* __restrict__ O)
{
    int bh = blockIdx.y;
    int b = bh >> 5, hh = bh & 31;
    int qi0 = blockIdx.x * 64;
    __shared__ float Ps[16][64];    // [ki][qi]
    __shared__ float Vs[16][128];   // [ki][d]
    int tid = threadIdx.x;
    int tx = tid & 31, ty = tid >> 5;   // tx: 32 col-groups of 4, ty: 8 row-groups of 8
    float acc[8][4] = {};
    const float* Pb = P + ((size_t)bh * SEQ + qi0) * SEQ;
    const float* Vb = V + (size_t)b * SEQ * DLLM + hh * HD;
    int pq = tid >> 2, pk4 = (tid & 3) * 4;
    int vk = tid >> 4, vd8 = (tid & 15) * 8;
    for (int k0 = 0; k0 < SEQ; k0 += 16) {
        float4 pv = *(const float4*)(Pb + (size_t)pq * SEQ + k0 + pk4);
        Ps[pk4+0][pq] = pv.x; Ps[pk4+1][pq] = pv.y; Ps[pk4+2][pq] = pv.z; Ps[pk4+3][pq] = pv.w;
        const float* src = Vb + (size_t)(k0 + vk) * DLLM + vd8;
        *(float4*)&Vs[vk][vd8]     = *(const float4*)(src);
        *(float4*)&Vs[vk][vd8 + 4] = *(const float4*)(src + 4);
        __syncthreads();
        #pragma unroll
        for (int kk = 0; kk < 16; kk++) {
            float a[8], bb[4];
            *(float4*)(a)     = *(const float4*)&Ps[kk][ty * 8];
            *(float4*)(a + 4) = *(const float4*)&Ps[kk][ty * 8 + 4];
            *(float4*)bb      = *(const float4*)&Vs[kk][tx * 4];
            #pragma unroll
            for (int i = 0; i < 8; i++)
                #pragma unroll
                for (int j = 0; j < 4; j++)
                    acc[i][j] = fmaf(a[i], bb[j], acc[i][j]);
        }
        __syncthreads();
    }
    #pragma unroll
    for (int i = 0; i < 8; i++) {
        int qi = qi0 + ty * 8 + i;
        float* dst = O + ((size_t)b * SEQ + qi) * DLLM + hh * HD + tx * 4;
        *(float4*)dst = make_float4(acc[i][0], acc[i][1], acc[i][2], acc[i][3]);
    }
}

// ---------------- Mean pool over sequence ----------------
__global__ __launch_bounds__(256)
void pool_kernel(const float* __restrict__ x, float* __restrict__ pooled)
{
    int b = blockIdx.x;
    int d = blockIdx.y * 256 + threadIdx.x;
    float s = 0.f;
    const float* base = x + (size_t)b * SEQ * DLLM + d;
    for (int t = 0; t < SEQ; t++) s += base[(size_t)t * DLLM];
    pooled[(size_t)b * DLLM + d] = s * (1.f / SEQ);
}

// ---------------- Output head ----------------
__global__ __launch_bounds__(256)
void out1_kernel(const float* __restrict__ pooled, const float* __restrict__ W,
                 const float* __restrict__ bias, float* __restrict__ y1)
{
    int b = blockIdx.x;
    int n = blockIdx.y * 256 + threadIdx.x;
    const float* pv = pooled + (size_t)b * DLLM;
    float acc = bias[n];
    for (int k = 0; k < DLLM; k++)
        acc = fmaf(pv[k], W[(size_t)k * 768 + n], acc);
    y1[(size_t)b * 768 + n] = acc;
}

__global__ __launch_bounds__(256)
void out2_kernel(const float* __restrict__ y1, const float* __restrict__ W2,
                 const float* __restrict__ b2, float* __restrict__ out)
{
    int b = blockIdx.x;
    int tid = threadIdx.x;
    __shared__ float red[8];
    float s = 0.f;
    for (int j = tid; j < 768; j += 256) s += y1[(size_t)b * 768 + j] * W2[j];
    #pragma unroll
    for (int o = 16; o; o >>= 1) s += __shfl_xor_sync(0xffffffffu, s, o);
    if ((tid & 31) == 0) red[tid >> 5] = s;
    __syncthreads();
    if (tid < 32) {
        float x = (tid < 8) ? red[tid] : 0.f;
        #pragma unroll
        for (int o = 4; o; o >>= 1) x += __shfl_xor_sync(0xffffffffu, x, o);
        if (tid == 0) out[b] = x + b2[0];
    }
}

// ---------------- Host orchestration ----------------
extern "C" void kernel_launch(void* const* d_in, const int* in_sizes, int n_in,
                              void* d_out, int out_size)
{
    const float* text    = (const float*)d_in[0];
    const float* vision  = (const float*)d_in[1];
    const int*   prompt  = (const int*)  d_in[2];
    const float* in_W    = (const float*)d_in[3];
    const float* in_b    = (const float*)d_in[4];
    const float* table   = (const float*)d_in[5];
    const float* Wq      = (const float*)d_in[6];
    const float* Wk      = (const float*)d_in[7];
    const float* Wv      = (const float*)d_in[8];
    const float* Wo      = (const float*)d_in[9];
    const float* ln1     = (const float*)d_in[10];
    const float* ln2     = (const float*)d_in[11];
    const float* Wg      = (const float*)d_in[12];
    const float* Wu      = (const float*)d_in[13];
    const float* Wd      = (const float*)d_in[14];
    const float* final_w = (const float*)d_in[15];
    const float* out1W   = (const float*)d_in[16];
    const float* out1b   = (const float*)d_in[17];
    const float* out2W   = (const float*)d_in[18];
    const float* out2b   = (const float*)d_in[19];
    float* out = (float*)d_out;

    float *h, *x, *q, *k, *v, *o, *sc, *ff, *pooled, *y1;
    cudaGetSymbolAddress((void**)&h,  g_h);
    cudaGetSymbolAddress((void**)&x,  g_x);
    cudaGetSymbolAddress((void**)&q,  g_q);
    cudaGetSymbolAddress((void**)&k,  g_k);
    cudaGetSymbolAddress((void**)&v,  g_v);
    cudaGetSymbolAddress((void**)&o,  g_o);
    cudaGetSymbolAddress((void**)&sc, g_sc);
    cudaGetSymbolAddress((void**)&ff, g_ff);
    cudaGetSymbolAddress((void**)&pooled, g_pool);
    cudaGetSymbolAddress((void**)&y1, g_y1);

    // ---- Input embeddings into concatenated h: [prompt(128) | text(64) | vision(64)] ----
    embed_kernel<<<B * S_P, 256>>>(prompt, table, h);
    // text:  M = B*S_T = 512, remap rows b*64+t -> b*256 + 128 + t
    sgemm_kernel<0><<<dim3(DLLM/128, (B*S_T)/128), 256>>>(
        B*S_T, DLLM, DMODEL, text,   in_W, in_b, h, S_T, SEQ, S_P);
    // vision: rows b*64+t -> b*256 + 192 + t
    sgemm_kernel<0><<<dim3(DLLM/128, (B*S_V)/128), 256>>>(
        B*S_V, DLLM, DMODEL, vision, in_W, in_b, h, S_V, SEQ, S_P + S_T);

    for (int l = 0; l < NLAYER; l++) {
        const float* wq = Wq + (size_t)l * DLLM * DLLM;
        const float* wk = Wk + (size_t)l * DLLM * DLLM;
        const float* wv = Wv + (size_t)l * DLLM * DLLM;
        const float* wo = Wo + (size_t)l * DLLM * DLLM;
        const float* wg = Wg + (size_t)l * DLLM * DFF;
        const float* wu = Wu + (size_t)l * DLLM * DFF;
        const float* wd = Wd + (size_t)l * DFF * DLLM;
        const float* l1 = ln1 + (size_t)l * DLLM;
        const float* l2 = ln2 + (size_t)l * DLLM;

        // --- attention block ---
        rmsnorm_kernel<<<NTOK, 256>>>(h, l1, x);
        sgemm_kernel<0><<<dim3(DLLM/128, NTOK/128), 256>>>(NTOK, DLLM, DLLM, x, wq, nullptr, q, NTOK, NTOK, 0);
        sgemm_kernel<0><<<dim3(DLLM/128, NTOK/128), 256>>>(NTOK, DLLM, DLLM, x, wk, nullptr, k, NTOK, NTOK, 0);
        sgemm_kernel<0><<<dim3(DLLM/128, NTOK/128), 256>>>(NTOK, DLLM, DLLM, x, wv, nullptr, v, NTOK, NTOK, 0);
        rope_kernel<<<NTOK, 256>>>(q, k);
        score_kernel<<<dim3(SEQ/64, SEQ/64, B*NH), 256>>>(q, k, sc);
        softmax_kernel<<<B*NH*SEQ, 256>>>(sc);
        av_kernel<<<dim3(SEQ/64, B*NH), 256>>>(sc, v, o);
        sgemm_kernel<1><<<dim3(DLLM/128, NTOK/128), 256>>>(NTOK, DLLM, DLLM, o, wo, nullptr, h, NTOK, NTOK, 0);

        // --- FFN block (SwiGLU) ---
        rmsnorm_kernel<<<NTOK, 256>>>(h, l2, x);
        sgemm_kernel<0><<<dim3(DFF/128, NTOK/128), 256>>>(NTOK, DFF, DLLM, x, wg, nullptr, ff, NTOK, NTOK, 0);
        sgemm_kernel<2><<<dim3(DFF/128, NTOK/128), 256>>>(NTOK, DFF, DLLM, x, wu, nullptr, ff, NTOK, NTOK, 0);
        sgemm_kernel<1><<<dim3(DLLM/128, NTOK/128), 256>>>(NTOK, DLLM, DFF, ff, wd, nullptr, h, NTOK, NTOK, 0);
    }

    // ---- final norm, pool, output head ----
    rmsnorm_kernel<<<NTOK, 256>>>(h, final_w, x);
    pool_kernel<<<dim3(B, DLLM/256), 256>>>(x, pooled);
    out1_kernel<<<dim3(B, 768/256), 256>>>(pooled, out1W, out1b, y1);
    out2_kernel<<<B, 256>>>(y1, out2W, out2b, out);
}

// round 10
// speedup vs baseline: 1.6036x; 1.6022x over previous
#include <cuda_runtime.h>
#include <cuda_bf16.h>
#include <math.h>
#include <stdint.h>

#define B      8
#define S_P    128
#define S_T    64
#define S_V    64
#define SEQ    256
#define DMODEL 768
#define DLLM   4096
#define NH     32
#define HD     128
#define DFF    11008
#define NLAYER 2
#define NTOK   (B*SEQ)
#define EPSRMS 1e-5f

__device__ float g_h [NTOK*DLLM];
__device__ float g_x [NTOK*DLLM];
__device__ float g_q [NTOK*DLLM];
__device__ float g_k [NTOK*DLLM];
__device__ float g_v [NTOK*DLLM];
__device__ float g_o [NTOK*DLLM];
__device__ float g_sc[B*NH*SEQ*SEQ];
__device__ float g_ff[NTOK*DFF];
__device__ float g_pool[B*DLLM];
__device__ float g_y1[B*768];

__device__ __forceinline__ float siluf(float x) { return x / (1.f + expf(-x)); }

// ======================= mma.sync plumbing =======================
__device__ __forceinline__ uint32_t smem_u32(const void* p) {
    uint32_t a;
    asm("{ .reg .u64 t; cvta.to.shared.u64 t, %1; cvt.u32.u64 %0, t; }" : "=r"(a) : "l"(p));
    return a;
}
#define LDSM4(R0,R1,R2,R3,addr) \
    asm volatile("ldmatrix.sync.aligned.m8n8.x4.shared.b16 {%0,%1,%2,%3}, [%4];" \
                 : "=r"(R0),"=r"(R1),"=r"(R2),"=r"(R3) : "r"(addr))
#define MMA(d, a, b) \
    asm volatile("mma.sync.aligned.m16n8k16.row.col.f32.bf16.bf16.f32 " \
        "{%0,%1,%2,%3},{%4,%5,%6,%7},{%8,%9},{%0,%1,%2,%3};" \
        : "+f"((d)[0]),"+f"((d)[1]),"+f"((d)[2]),"+f"((d)[3]) \
        : "r"((a)[0]),"r"((a)[1]),"r"((a)[2]),"r"((a)[3]),"r"((b)[0]),"r"((b)[1]))

// fp32 -> (hi, lo) bf16 pairs; first arg in low 16 bits
__device__ __forceinline__ void split2(float a, float b, uint32_t& hi, uint32_t& lo) {
    __nv_bfloat162 h = __floats2bfloat162_rn(a, b);
    float2 hf = __bfloat1622float2(h);
    __nv_bfloat162 l = __floats2bfloat162_rn(a - hf.x, b - hf.y);
    hi = *reinterpret_cast<uint32_t*>(&h);
    lo = *reinterpret_cast<uint32_t*>(&l);
}

// Tile rows are 32 bf16 = 64B = four 16B chunks; XOR-swizzle chunks by row
// so ldmatrix 8-row phases hit all 32 banks (conflict-free).
__device__ __forceinline__ uint32_t swz(int r, int cChunk) {
    return (uint32_t)(r * 64 + (((cChunk) ^ ((r >> 1) & 3)) << 4));
}

// ====== split-bf16 tensor GEMM: C[M,N] (+)= A[M,K]@B[K,N], fp32 io ======
// CTA 128x128, K-stage 32, 256 thr (8 warps = 2m x 4n, warp tile 64x32).
// EPI: 0=store(+bias), 1=C+=acc, 2=C=silu(C)*acc.  orow=(r/rpbi)*rpbo+roff+r%rpbi
template<int EPI>
__global__ __launch_bounds__(256)
void gemm_mma(int M, int N, int K,
              const float* __restrict__ A, const float* __restrict__ Bm,
              const float* __restrict__ bias, float* __restrict__ C,
              int rpbi, int rpbo, int roff)
{
    __shared__ __align__(16) char sm[32768];   // ah | al | bh | bl (8KB each)
    const uint32_t sb = smem_u32(sm);
    const uint32_t ahS = sb, alS = sb + 8192, bhS = sb + 16384, blS = sb + 24576;
    const int tid = threadIdx.x, lane = tid & 31, wid = tid >> 5;
    const int gm0 = blockIdx.x * 128, gn0 = blockIdx.y * 128;
    const int wm = (wid & 1) * 64, wn = (wid >> 1) * 32;

    float acc[4][4][4] = {};

    // producer indices
    const int par = tid >> 3;            // A row base (+32p)
    const int pak = (tid & 7) * 4;       // A k elems (float4)
    const int pbk = wid * 2 + (lane >> 4);   // B k-pair 0..15
    const int pbn = (lane & 15) * 2;         // B n base (+32i)

    float4 aReg[4];
    float2 bReg[4][2];

    auto loadG = [&](int k0) {
        const float* Ag = A + (size_t)(gm0 + par) * K + k0 + pak;
        #pragma unroll
        for (int p = 0; p < 4; p++)
            aReg[p] = *(const float4*)(Ag + (size_t)(32 * p) * K);
        const float* Bg = Bm + (size_t)(k0 + 2 * pbk) * N + gn0 + pbn;
        #pragma unroll
        for (int i = 0; i < 4; i++) {
            bReg[i][0] = *(const float2*)(Bg + 32 * i);
            bReg[i][1] = *(const float2*)(Bg + N + 32 * i);
        }
    };
    auto storeS = [&]() {
        #pragma unroll
        for (int p = 0; p < 4; p++) {
            int r = par + 32 * p;
            uint32_t h0, l0, h1, l1;
            split2(aReg[p].x, aReg[p].y, h0, l0);
            split2(aReg[p].z, aReg[p].w, h1, l1);
            uint32_t off = swz(r, pak >> 3) + ((pak & 4) << 1);
            *(uint2*)(sm + off)        = make_uint2(h0, h1);
            *(uint2*)(sm + 8192 + off) = make_uint2(l0, l1);
        }
        #pragma unroll
        for (int i = 0; i < 4; i++) {
            int n = pbn + 32 * i;
            uint32_t hp0, lp0, hp1, lp1;
            split2(bReg[i][0].x, bReg[i][1].x, hp0, lp0);   // (k, k+1) at n
            split2(bReg[i][0].y, bReg[i][1].y, hp1, lp1);   // (k, k+1) at n+1
            uint32_t inner = (uint32_t)((pbk & 3) << 2);
            uint32_t o0 = swz(n, pbk >> 2) + inner;
            uint32_t o1 = swz(n + 1, pbk >> 2) + inner;
            *(uint32_t*)(sm + 16384 + o0) = hp0;
            *(uint32_t*)(sm + 24576 + o0) = lp0;
            *(uint32_t*)(sm + 16384 + o1) = hp1;
            *(uint32_t*)(sm + 24576 + o1) = lp1;
        }
    };
    auto computeHalf = [&](int ks) {
        uint32_t aH[4][4], aL[4][4], bH[4][2], bL[4][2];
        int cb = (ks >> 3) + (lane >> 4);
        #pragma unroll
        for (int mi = 0; mi < 4; mi++) {
            uint32_t off = swz(wm + mi * 16 + (lane & 15), cb);
            LDSM4(aH[mi][0], aH[mi][1], aH[mi][2], aH[mi][3], ahS + off);
            LDSM4(aL[mi][0], aL[mi][1], aL[mi][2], aL[mi][3], alS + off);
        }
        #pragma unroll
        for (int nh = 0; nh < 2; nh++) {
            uint32_t off = swz(wn + nh * 16 + (lane & 15), cb);
            uint32_t r0, r1, r2, r3;
            LDSM4(r0, r1, r2, r3, bhS + off);
            bH[2*nh][0] = r0; bH[2*nh][1] = r2; bH[2*nh+1][0] = r1; bH[2*nh+1][1] = r3;
            LDSM4(r0, r1, r2, r3, blS + off);
            bL[2*nh][0] = r0; bL[2*nh][1] = r2; bL[2*nh+1][0] = r1; bL[2*nh+1][1] = r3;
        }
        #pragma unroll
        for (int mi = 0; mi < 4; mi++)
            #pragma unroll
            for (int ni = 0; ni < 4; ni++) {
                MMA(acc[mi][ni], aH[mi], bH[ni]);
                MMA(acc[mi][ni], aH[mi], bL[ni]);
                MMA(acc[mi][ni], aL[mi], bH[ni]);
            }
    };

    const int nst = K / 32;
    loadG(0);
    for (int s = 0; s < nst; s++) {
        __syncthreads();
        storeS();
        __syncthreads();
        if (s + 1 < nst) loadG((s + 1) * 32);
        computeHalf(0);
        computeHalf(16);
    }

    // ---- epilogue ----
    #pragma unroll
    for (int mi = 0; mi < 4; mi++) {
        int rbase = gm0 + wm + mi * 16 + (lane >> 2);
        #pragma unroll
        for (int half = 0; half < 2; half++) {
            int r = rbase + half * 8;
            int orow = (r / rpbi) * rpbo + roff + (r % rpbi);
            float* Crow = C + (size_t)orow * N;
            #pragma unroll
            for (int ni = 0; ni < 4; ni++) {
                int col = gn0 + wn + ni * 8 + (lane & 3) * 2;
                float v0 = acc[mi][ni][half * 2 + 0];
                float v1 = acc[mi][ni][half * 2 + 1];
                float* d = Crow + col;
                if (EPI == 0) {
                    if (bias) { v0 += bias[col]; v1 += bias[col + 1]; }
                    d[0] = v0; d[1] = v1;
                } else if (EPI == 1) {
                    d[0] += v0; d[1] += v1;
                } else {
                    d[0] = siluf(d[0]) * v0; d[1] = siluf(d[1]) * v1;
                }
            }
        }
    }
}

// ======================= auxiliary kernels (unchanged) =======================
__global__ __launch_bounds__(256)
void embed_kernel(const int* __restrict__ ids, const float* __restrict__ table,
                  float* __restrict__ h)
{
    int t = blockIdx.x;
    int b = t >> 7, p = t & 127;
    int id = ids[t];
    const float4* src = (const float4*)(table + (size_t)id * DLLM);
    float4* dst = (float4*)(h + ((size_t)b * SEQ + p) * DLLM);
    for (int i = threadIdx.x; i < DLLM / 4; i += 256) dst[i] = src[i];
}

__global__ __launch_bounds__(256)
void rmsnorm_kernel(const float* __restrict__ in, const float* __restrict__ w,
                    float* __restrict__ out)
{
    size_t t = blockIdx.x;
    const float4* xp = (const float4*)(in + t * DLLM);
    __shared__ float red[8];
    float ss = 0.f;
    for (int i = threadIdx.x; i < DLLM / 4; i += 256) {
        float4 v = xp[i];
        ss += v.x*v.x + v.y*v.y + v.z*v.z + v.w*v.w;
    }
    #pragma unroll
    for (int o = 16; o; o >>= 1) ss += __shfl_xor_sync(0xffffffffu, ss, o);
    if ((threadIdx.x & 31) == 0) red[threadIdx.x >> 5] = ss;
    __syncthreads();
    if (threadIdx.x < 32) {
        float v = (threadIdx.x < 8) ? red[threadIdx.x] : 0.f;
        #pragma unroll
        for (int o = 4; o; o >>= 1) v += __shfl_xor_sync(0xffffffffu, v, o);
        if (threadIdx.x == 0) red[0] = v;
    }
    __syncthreads();
    float r = rsqrtf(red[0] / (float)DLLM + EPSRMS);
    const float4* wp = (const float4*)w;
    float4* op = (float4*)(out + t * DLLM);
    for (int i = threadIdx.x; i < DLLM / 4; i += 256) {
        float4 v = xp[i], wv = wp[i];
        op[i] = make_float4(v.x*r*wv.x, v.y*r*wv.y, v.z*r*wv.z, v.w*r*wv.w);
    }
}

__global__ __launch_bounds__(256)
void rope_kernel(float* __restrict__ q, float* __restrict__ k)
{
    int t = blockIdx.x;
    int pos = t & (SEQ - 1);
    const float LOG_THETA = 9.210340371976184f;
    for (int it = 0; it < 8; it++) {
        int p = threadIdx.x + it * 256;
        int hh = p >> 6, j = p & 63;
        float inv_freq = expf(-(float)j * (LOG_THETA / 64.f));
        float ang = (float)pos * inv_freq;
        float c = cosf(ang), s = sinf(ang);
        size_t base = (size_t)t * DLLM + hh * HD + j;
        float x1 = q[base], x2 = q[base + 64];
        q[base]      = x1 * c - x2 * s;
        q[base + 64] = x2 * c + x1 * s;
        x1 = k[base]; x2 = k[base + 64];
        k[base]      = x1 * c - x2 * s;
        k[base + 64] = x2 * c + x1 * s;
    }
}

__global__ __launch_bounds__(256)
void score_kernel(const float* __restrict__ Q, const float* __restrict__ K,
                  float* __restrict__ Sc)
{
    int bh = blockIdx.z;
    int b = bh >> 5, hh = bh & 31;
    int qi0 = blockIdx.y * 64, kj0 = blockIdx.x * 64;
    __shared__ float As[16][64];
    __shared__ float Bs[16][64];
    int tid = threadIdx.x;
    int tx = tid & 15, ty = tid >> 4;
    float acc[4][4] = {};
    const float* Qb = Q + ((size_t)b * SEQ + qi0) * DLLM + hh * HD;
    const float* Kb = K + ((size_t)b * SEQ + kj0) * DLLM + hh * HD;
    int r  = tid >> 2;
    int c4 = (tid & 3) * 4;
    for (int k0 = 0; k0 < HD; k0 += 16) {
        float4 qa = *(const float4*)(Qb + (size_t)r * DLLM + k0 + c4);
        As[c4+0][r] = qa.x; As[c4+1][r] = qa.y; As[c4+2][r] = qa.z; As[c4+3][r] = qa.w;
        float4 ka = *(const float4*)(Kb + (size_t)r * DLLM + k0 + c4);
        Bs[c4+0][r] = ka.x; Bs[c4+1][r] = ka.y; Bs[c4+2][r] = ka.z; Bs[c4+3][r] = ka.w;
        __syncthreads();
        #pragma unroll
        for (int kk = 0; kk < 16; kk++) {
            float a[4], bb[4];
            *(float4*)a  = *(const float4*)&As[kk][ty * 4];
            *(float4*)bb = *(const float4*)&Bs[kk][tx * 4];
            #pragma unroll
            for (int i = 0; i < 4; i++)
                #pragma unroll
                for (int j = 0; j < 4; j++)
                    acc[i][j] = fmaf(a[i], bb[j], acc[i][j]);
        }
        __syncthreads();
    }
    const float scale = 0.08838834764831845f;
    #pragma unroll
    for (int i = 0; i < 4; i++) {
        int qi = qi0 + ty * 4 + i;
        float* dst = Sc + ((size_t)bh * SEQ + qi) * SEQ + kj0 + tx * 4;
        #pragma unroll
        for (int j = 0; j < 4; j++) {
            int kj = kj0 + tx * 4 + j;
            dst[j] = (kj > qi) ? -1e30f : acc[i][j] * scale;
        }
    }
}

__global__ __launch_bounds__(256)
void softmax_kernel(float* __restrict__ Sc)
{
    float* p = Sc + (size_t)blockIdx.x * SEQ;
    int tid = threadIdx.x;
    __shared__ float redm[8], reds[8];
    float v = p[tid];
    float m = v;
    #pragma unroll
    for (int o = 16; o; o >>= 1) m = fmaxf(m, __shfl_xor_sync(0xffffffffu, m, o));
    if ((tid & 31) == 0) redm[tid >> 5] = m;
    __syncthreads();
    if (tid < 32) {
        float x = (tid < 8) ? redm[tid] : -3.4e38f;
        #pragma unroll
        for (int o = 4; o; o >>= 1) x = fmaxf(x, __shfl_xor_sync(0xffffffffu, x, o));
        if (tid == 0) redm[0] = x;
    }
    __syncthreads();
    m = redm[0];
    float e = expf(v - m);
    float s = e;
    #pragma unroll
    for (int o = 16; o; o >>= 1) s += __shfl_xor_sync(0xffffffffu, s, o);
    if ((tid & 31) == 0) reds[tid >> 5] = s;
    __syncthreads();
    if (tid < 32) {
        float x = (tid < 8) ? reds[tid] : 0.f;
        #pragma unroll
        for (int o = 4; o; o >>= 1) x += __shfl_xor_sync(0xffffffffu, x, o);
        if (tid == 0) reds[0] = x;
    }
    __syncthreads();
    p[tid] = e / reds[0];
}

__global__ __launch_bounds__(256)
void av_kernel(const float* __restrict__ P, const float* __restrict__ V,
               float* __restrict__ O)
{
    int bh = blockIdx.y;
    int b = bh >> 5, hh = bh & 31;
    int qi0 = blockIdx.x * 64;
    __shared__ float Ps[16][64];
    __shared__ float Vs[16][128];
    int tid = threadIdx.x;
    int tx = tid & 31, ty = tid >> 5;
    float acc[8][4] = {};
    const float* Pb = P + ((size_t)bh * SEQ + qi0) * SEQ;
    const float* Vb = V + (size_t)b * SEQ * DLLM + hh * HD;
    int pq = tid >> 2, pk4 = (tid & 3) * 4;
    int vk = tid >> 4, vd8 = (tid & 15) * 8;
    for (int k0 = 0; k0 < SEQ; k0 += 16) {
        float4 pv = *(const float4*)(Pb + (size_t)pq * SEQ + k0 + pk4);
        Ps[pk4+0][pq] = pv.x; Ps[pk4+1][pq] = pv.y; Ps[pk4+2][pq] = pv.z; Ps[pk4+3][pq] = pv.w;
        const float* src = Vb + (size_t)(k0 + vk) * DLLM + vd8;
        *(float4*)&Vs[vk][vd8]     = *(const float4*)(src);
        *(float4*)&Vs[vk][vd8 + 4] = *(const float4*)(src + 4);
        __syncthreads();
        #pragma unroll
        for (int kk = 0; kk < 16; kk++) {
            float a[8], bb[4];
            *(float4*)(a)     = *(const float4*)&Ps[kk][ty * 8];
            *(float4*)(a + 4) = *(const float4*)&Ps[kk][ty * 8 + 4];
            *(float4*)bb      = *(const float4*)&Vs[kk][tx * 4];
            #pragma unroll
            for (int i = 0; i < 8; i++)
                #pragma unroll
                for (int j = 0; j < 4; j++)
                    acc[i][j] = fmaf(a[i], bb[j], acc[i][j]);
        }
        __syncthreads();
    }
    #pragma unroll
    for (int i = 0; i < 8; i++) {
        int qi = qi0 + ty * 8 + i;
        float* dst = O + ((size_t)b * SEQ + qi) * DLLM + hh * HD + tx * 4;
        *(float4*)dst = make_float4(acc[i][0], acc[i][1], acc[i][2], acc[i][3]);
    }
}

__global__ __launch_bounds__(256)
void pool_kernel(const float* __restrict__ x, float* __restrict__ pooled)
{
    int b = blockIdx.x;
    int d = blockIdx.y * 256 + threadIdx.x;
    float s = 0.f;
    const float* base = x + (size_t)b * SEQ * DLLM + d;
    for (int t = 0; t < SEQ; t++) s += base[(size_t)t * DLLM];
    pooled[(size_t)b * DLLM + d] = s * (1.f / SEQ);
}

__global__ __launch_bounds__(256)
void out1_kernel(const float* __restrict__ pooled, const float* __restrict__ W,
                 const float* __restrict__ bias, float* __restrict__ y1)
{
    int b = blockIdx.x;
    int n = blockIdx.y * 256 + threadIdx.x;
    const float* pv = pooled + (size_t)b * DLLM;
    float acc = bias[n];
    for (int k = 0; k < DLLM; k++)
        acc = fmaf(pv[k], W[(size_t)k * 768 + n], acc);
    y1[(size_t)b * 768 + n] = acc;
}

__global__ __launch_bounds__(256)
void out2_kernel(const float* __restrict__ y1, const float* __restrict__ W2,
                 const float* __restrict__ b2, float* __restrict__ out)
{
    int b = blockIdx.x;
    int tid = threadIdx.x;
    __shared__ float red[8];
    float s = 0.f;
    for (int j = tid; j < 768; j += 256) s += y1[(size_t)b * 768 + j] * W2[j];
    #pragma unroll
    for (int o = 16; o; o >>= 1) s += __shfl_xor_sync(0xffffffffu, s, o);
    if ((tid & 31) == 0) red[tid >> 5] = s;
    __syncthreads();
    if (tid < 32) {
        float x = (tid < 8) ? red[tid] : 0.f;
        #pragma unroll
        for (int o = 4; o; o >>= 1) x += __shfl_xor_sync(0xffffffffu, x, o);
        if (tid == 0) out[b] = x + b2[0];
    }
}

// ======================= host orchestration =======================
extern "C" void kernel_launch(void* const* d_in, const int* in_sizes, int n_in,
                              void* d_out, int out_size)
{
    const float* text    = (const float*)d_in[0];
    const float* vision  = (const float*)d_in[1];
    const int*   prompt  = (const int*)  d_in[2];
    const float* in_W    = (const float*)d_in[3];
    const float* in_b    = (const float*)d_in[4];
    const float* table   = (const float*)d_in[5];
    const float* Wq      = (const float*)d_in[6];
    const float* Wk      = (const float*)d_in[7];
    const float* Wv      = (const float*)d_in[8];
    const float* Wo      = (const float*)d_in[9];
    const float* ln1     = (const float*)d_in[10];
    const float* ln2     = (const float*)d_in[11];
    const float* Wg      = (const float*)d_in[12];
    const float* Wu      = (const float*)d_in[13];
    const float* Wd      = (const float*)d_in[14];
    const float* final_w = (const float*)d_in[15];
    const float* out1W   = (const float*)d_in[16];
    const float* out1b   = (const float*)d_in[17];
    const float* out2W   = (const float*)d_in[18];
    const float* out2b   = (const float*)d_in[19];
    float* out = (float*)d_out;

    float *h, *x, *q, *k, *v, *o, *sc, *ff, *pooled, *y1;
    cudaGetSymbolAddress((void**)&h,  g_h);
    cudaGetSymbolAddress((void**)&x,  g_x);
    cudaGetSymbolAddress((void**)&q,  g_q);
    cudaGetSymbolAddress((void**)&k,  g_k);
    cudaGetSymbolAddress((void**)&v,  g_v);
    cudaGetSymbolAddress((void**)&o,  g_o);
    cudaGetSymbolAddress((void**)&sc, g_sc);
    cudaGetSymbolAddress((void**)&ff, g_ff);
    cudaGetSymbolAddress((void**)&pooled, g_pool);
    cudaGetSymbolAddress((void**)&y1, g_y1);

    // ---- inputs into concatenated h: [prompt(128) | text(64) | vision(64)] ----
    embed_kernel<<<B * S_P, 256>>>(prompt, table, h);
    gemm_mma<0><<<dim3((B*S_T)/128, DLLM/128), 256>>>(
        B*S_T, DLLM, DMODEL, text,   in_W, in_b, h, S_T, SEQ, S_P);
    gemm_mma<0><<<dim3((B*S_V)/128, DLLM/128), 256>>>(
        B*S_V, DLLM, DMODEL, vision, in_W, in_b, h, S_V, SEQ, S_P + S_T);

    for (int l = 0; l < NLAYER; l++) {
        const float* wq = Wq + (size_t)l * DLLM * DLLM;
        const float* wk = Wk + (size_t)l * DLLM * DLLM;
        const float* wv = Wv + (size_t)l * DLLM * DLLM;
        const float* wo = Wo + (size_t)l * DLLM * DLLM;
        const float* wg = Wg + (size_t)l * DLLM * DFF;
        const float* wu = Wu + (size_t)l * DLLM * DFF;
        const float* wd = Wd + (size_t)l * DFF * DLLM;
        const float* l1 = ln1 + (size_t)l * DLLM;
        const float* l2 = ln2 + (size_t)l * DLLM;

        rmsnorm_kernel<<<NTOK, 256>>>(h, l1, x);
        gemm_mma<0><<<dim3(NTOK/128, DLLM/128), 256>>>(NTOK, DLLM, DLLM, x, wq, nullptr, q, NTOK, NTOK, 0);
        gemm_mma<0><<<dim3(NTOK/128, DLLM/128), 256>>>(NTOK, DLLM, DLLM, x, wk, nullptr, k, NTOK, NTOK, 0);
        gemm_mma<0><<<dim3(NTOK/128, DLLM/128), 256>>>(NTOK, DLLM, DLLM, x, wv, nullptr, v, NTOK, NTOK, 0);
        rope_kernel<<<NTOK, 256>>>(q, k);
        score_kernel<<<dim3(SEQ/64, SEQ/64, B*NH), 256>>>(q, k, sc);
        softmax_kernel<<<B*NH*SEQ, 256>>>(sc);
        av_kernel<<<dim3(SEQ/64, B*NH), 256>>>(sc, v, o);
        gemm_mma<1><<<dim3(NTOK/128, DLLM/128), 256>>>(NTOK, DLLM, DLLM, o, wo, nullptr, h, NTOK, NTOK, 0);

        rmsnorm_kernel<<<NTOK, 256>>>(h, l2, x);
        gemm_mma<0><<<dim3(NTOK/128, DFF/128), 256>>>(NTOK, DFF, DLLM, x, wg, nullptr, ff, NTOK, NTOK, 0);
        gemm_mma<2><<<dim3(NTOK/128, DFF/128), 256>>>(NTOK, DFF, DLLM, x, wu, nullptr, ff, NTOK, NTOK, 0);
        gemm_mma<1><<<dim3(NTOK/128, DLLM/128), 256>>>(NTOK, DLLM, DFF, ff, wd, nullptr, h, NTOK, NTOK, 0);
    }

    rmsnorm_kernel<<<NTOK, 256>>>(h, final_w, x);
    pool_kernel<<<dim3(B, DLLM/256), 256>>>(x, pooled);
    out1_kernel<<<dim3(B, 768/256), 256>>>(pooled, out1W, out1b, y1);
    out2_kernel<<<B, 256>>>(y1, out2W, out2b, out);
}